// round 1
// baseline (speedup 1.0000x reference)
#include <cuda_runtime.h>

#define NN 10000
#define NE 40000
#define NG 64
#define H  64
#define QC 4160   // 64*64 (theta cols) + 64 (b2 term)

// ---------------- scratch (static device globals; no allocs) ----------------
__device__ float g_h0[NN*H];
__device__ float g_h1[NN*H];
__device__ float g_Q[(size_t)NN*QC];     // ~166 MB
__device__ float g_agg[NN*H];
__device__ float g_W2ext[H*QC];          // permuted edge_w2 (+b2) for current layer
__device__ float g_deg[NN];
__device__ float g_invdeg[NN];
__device__ float g_hg[NG*H];
__device__ float g_gcnt[NG];

__device__ __forceinline__ float siluf(float x){
    return x * (1.0f/(1.0f+__expf(-x)));
}

// ---------------- degree ----------------
__global__ void k_deg(const int* __restrict__ ei){
    int e = blockIdx.x*256 + threadIdx.x;
    if(e < NE) atomicAdd(&g_deg[ei[NE + e]], 1.0f);
}

__global__ void k_invdeg(){
    int v = blockIdx.x*256 + threadIdx.x;
    if(v < NN){ float d = g_deg[v]; g_invdeg[v] = (d > 0.f) ? 1.0f/d : 0.0f; }
}

// ---------------- node-side [*,64]@[64,64] with fused epilogue ----------------
// mode 0: out = A@W + b                      (input projection)
// mode 1: out = silu(agg*invdeg + A@W + b)   (layer update, root term)
__global__ void k_nodemm(const float* __restrict__ A, float* __restrict__ out,
                         const float* __restrict__ W, const float* __restrict__ b,
                         int mode){
    __shared__ float Ws[H*H];
    __shared__ float As[64][H+1];
    int t = threadIdx.x;
    int base = blockIdx.x*64;
    for(int i=t;i<H*H;i+=256) Ws[i]=W[i];
    for(int i=t;i<64*H;i+=256){
        int r=i>>6, c=i&63; int v=base+r;
        As[r][c] = (v<NN) ? A[v*H+c] : 0.f;
    }
    __syncthreads();
    int vl=t>>2, ob=(t&3)*16;
    int v=base+vl;
    if(v>=NN) return;
    float acc[16];
    #pragma unroll
    for(int q=0;q<16;q++) acc[q]=b[ob+q];
    #pragma unroll 8
    for(int i=0;i<H;i++){
        float hv=As[vl][i];
        #pragma unroll
        for(int q=0;q<16;q++) acc[q] += hv*Ws[i*H+ob+q];
    }
    if(mode==0){
        #pragma unroll
        for(int q=0;q<16;q++) out[v*H+ob+q]=acc[q];
    } else {
        float inv = g_invdeg[v];
        #pragma unroll
        for(int q=0;q<16;q++){
            float val = g_agg[v*H+ob+q]*inv + acc[q];
            out[v*H+ob+q] = siluf(val);
        }
    }
}

// ---------------- permute edge_w2[l] (j,i*64+o) -> W2ext (i, j*64+o | 4096+o=b2) ----------------
__global__ void k_transp(const float* __restrict__ w2, const float* __restrict__ b2){
    int idx = blockIdx.x*256 + threadIdx.x;
    if(idx < H*QC){
        int i = idx / QC;
        int c = idx % QC;
        float v;
        if(c < 4096){
            int j = c>>6, o = c&63;
            v = w2[j*4096 + i*64 + o];
        } else {
            v = b2[i*64 + (c-4096)];
        }
        g_W2ext[idx] = v;
    }
}

// ---------------- Q = h @ W2ext : [10000,64]@[64,4160] fp32 GEMM ----------------
// BM=64, BN=128, full K=64 in smem; 256 threads, each 4x8 accumulators.
__global__ void k_qgemm(const float* __restrict__ hin){
    __shared__ float As[64][64];    // [k][m]  (transposed)
    __shared__ float Bs[64][128];   // [k][n]
    int t = threadIdx.x;
    int bn = blockIdx.x*128;
    int bm = blockIdx.y*64;

    // load A tile transposed (rows contiguous since H==64)
    {
        int r = t>>2, c0 = (t&3)*16;
        int gr = bm + r;
        float4 v0,v1,v2,v3;
        if(gr < NN){
            const float4* p = (const float4*)(hin + gr*H + c0);
            v0=p[0]; v1=p[1]; v2=p[2]; v3=p[3];
        } else {
            v0=v1=v2=v3=make_float4(0.f,0.f,0.f,0.f);
        }
        As[c0+ 0][r]=v0.x; As[c0+ 1][r]=v0.y; As[c0+ 2][r]=v0.z; As[c0+ 3][r]=v0.w;
        As[c0+ 4][r]=v1.x; As[c0+ 5][r]=v1.y; As[c0+ 6][r]=v1.z; As[c0+ 7][r]=v1.w;
        As[c0+ 8][r]=v2.x; As[c0+ 9][r]=v2.y; As[c0+10][r]=v2.z; As[c0+11][r]=v2.w;
        As[c0+12][r]=v3.x; As[c0+13][r]=v3.y; As[c0+14][r]=v3.z; As[c0+15][r]=v3.w;
    }
    // load B tile
    for(int i=t;i<64*32;i+=256){
        int r = i>>5, c = (i&31)*4;
        float4 val;
        if(bn + c < QC) val = *(const float4*)(g_W2ext + r*QC + bn + c);
        else            val = make_float4(0.f,0.f,0.f,0.f);
        *(float4*)&Bs[r][c] = val;
    }
    __syncthreads();

    int tx = t&15, ty = t>>4;
    float acc[4][8];
    #pragma unroll
    for(int i=0;i<4;i++)
        #pragma unroll
        for(int j=0;j<8;j++) acc[i][j]=0.f;

    #pragma unroll 16
    for(int k=0;k<64;k++){
        float4 a  = *(const float4*)&As[k][ty*4];
        float4 b0 = *(const float4*)&Bs[k][tx*8];
        float4 b1 = *(const float4*)&Bs[k][tx*8+4];
        float av[4] = {a.x,a.y,a.z,a.w};
        float bv[8] = {b0.x,b0.y,b0.z,b0.w,b1.x,b1.y,b1.z,b1.w};
        #pragma unroll
        for(int i=0;i<4;i++)
            #pragma unroll
            for(int j=0;j<8;j++) acc[i][j] += av[i]*bv[j];
    }

    #pragma unroll
    for(int i=0;i<4;i++){
        int row = bm + ty*4 + i;
        if(row < NN){
            int col = bn + tx*8;
            if(col < QC){
                float4 o0 = make_float4(acc[i][0],acc[i][1],acc[i][2],acc[i][3]);
                float4 o1 = make_float4(acc[i][4],acc[i][5],acc[i][6],acc[i][7]);
                *(float4*)(g_Q + (size_t)row*QC + col)     = o0;
                *(float4*)(g_Q + (size_t)row*QC + col + 4) = o1;
            }
        }
    }
}

// ---------------- per-edge message: sfeat on the fly, dot with Q[src], scatter to agg[dst] ----------------
// 4 edges per block, 64 threads per edge (one output each).
__global__ void k_msg(const float* __restrict__ ea, const int* __restrict__ ei,
                      const float* __restrict__ w1, const float* __restrict__ b1){
    __shared__ float W1s[16*64];
    __shared__ float b1s[64];
    __shared__ float sf[4][64];
    int t = threadIdx.x;
    for(int i=t;i<16*64;i+=256) W1s[i]=w1[i];
    if(t<64) b1s[t]=b1[t];
    __syncthreads();

    int el = t>>6;
    int o  = t&63;
    int e  = blockIdx.x*4 + el;
    int src=0, dst=0;
    if(e < NE){
        src = ei[e];
        dst = ei[NE + e];
        const float* eap = ea + e*16;
        float s = b1s[o];
        #pragma unroll
        for(int j=0;j<16;j++) s += eap[j]*W1s[j*64+o];
        sf[el][o] = siluf(s);
    }
    __syncthreads();
    if(e < NE){
        const float* q = g_Q + (size_t)src*QC;
        float msg = q[4096 + o];         // b2 contribution (h_src @ B2)
        #pragma unroll 8
        for(int j=0;j<64;j++) msg += sf[el][j]*q[j*64 + o];
        atomicAdd(&g_agg[dst*H + o], msg);
    }
}

// ---------------- global mean pool ----------------
__global__ void k_pool(const int* __restrict__ batch, const float* __restrict__ hfin){
    int idx = blockIdx.x*256 + threadIdx.x;
    if(idx < NN*H){
        int v = idx>>6, o = idx&63;
        int g = batch[v];
        atomicAdd(&g_hg[g*H + o], hfin[idx]);
        if(o == 0) atomicAdd(&g_gcnt[g], 1.0f);
    }
}

// ---------------- head MLP: [64,64] -> silu -> [64,1] ----------------
__global__ void k_head(const float* __restrict__ w1, const float* __restrict__ b1,
                       const float* __restrict__ w2, const float* __restrict__ b2,
                       float* __restrict__ out){
    __shared__ float W1s[64*64];
    __shared__ float hgn[64*64];
    __shared__ float t1[64*64];
    int t = threadIdx.x;
    for(int i=t;i<4096;i+=256) W1s[i]=w1[i];
    for(int i=t;i<4096;i+=256){
        int g = i>>6;
        float c = g_gcnt[g];
        hgn[i] = g_hg[i] / fmaxf(c, 1.0f);
    }
    __syncthreads();
    int g = t>>2, ob = (t&3)*16;
    float acc[16];
    #pragma unroll
    for(int q=0;q<16;q++) acc[q]=b1[ob+q];
    for(int i=0;i<64;i++){
        float hv = hgn[g*64+i];
        #pragma unroll
        for(int q=0;q<16;q++) acc[q] += hv*W1s[i*64+ob+q];
    }
    #pragma unroll
    for(int q=0;q<16;q++) t1[g*64+ob+q] = siluf(acc[q]);
    __syncthreads();
    if(t < 64){
        float s = b2[0];
        for(int o=0;o<64;o++) s += t1[t*64+o]*w2[o];
        out[t] = s;
    }
}

// ---------------- launch ----------------
extern "C" void kernel_launch(void* const* d_in, const int* in_sizes, int n_in,
                              void* d_out, int out_size){
    const float* x         = (const float*)d_in[0];
    const float* edge_attr = (const float*)d_in[1];
    const int*   edge_index= (const int*)  d_in[2];
    const int*   batch     = (const int*)  d_in[3];
    const float* proj_w    = (const float*)d_in[4];
    const float* proj_b    = (const float*)d_in[5];
    const float* edge_w1   = (const float*)d_in[6];   // [3,16,64]
    const float* edge_b1   = (const float*)d_in[7];   // [3,64]
    const float* edge_w2   = (const float*)d_in[8];   // [3,64,4096]
    const float* edge_b2   = (const float*)d_in[9];   // [3,4096]
    const float* root_w    = (const float*)d_in[10];  // [3,64,64]
    const float* conv_b    = (const float*)d_in[11];  // [3,64]
    const float* head_w1   = (const float*)d_in[12];
    const float* head_b1   = (const float*)d_in[13];
    const float* head_w2   = (const float*)d_in[14];
    const float* head_b2   = (const float*)d_in[15];
    float* out = (float*)d_out;

    void *p_deg, *p_agg, *p_hg, *p_gcnt, *p_h0, *p_h1;
    cudaGetSymbolAddress(&p_deg,  g_deg);
    cudaGetSymbolAddress(&p_agg,  g_agg);
    cudaGetSymbolAddress(&p_hg,   g_hg);
    cudaGetSymbolAddress(&p_gcnt, g_gcnt);
    cudaGetSymbolAddress(&p_h0,   g_h0);
    cudaGetSymbolAddress(&p_h1,   g_h1);
    float* h0 = (float*)p_h0;
    float* h1 = (float*)p_h1;

    cudaMemsetAsync(p_deg,  0, NN*sizeof(float));
    cudaMemsetAsync(p_hg,   0, NG*H*sizeof(float));
    cudaMemsetAsync(p_gcnt, 0, NG*sizeof(float));

    k_deg<<<(NE+255)/256, 256>>>(edge_index);
    k_invdeg<<<(NN+255)/256, 256>>>();

    float* cur = h0;
    float* nxt = h1;
    k_nodemm<<<(NN+63)/64, 256>>>(x, cur, proj_w, proj_b, 0);

    for(int l=0;l<3;l++){
        k_transp<<<(H*QC+255)/256, 256>>>(edge_w2 + (size_t)l*64*4096, edge_b2 + (size_t)l*4096);
        k_qgemm<<<dim3((QC+127)/128, (NN+63)/64), 256>>>(cur);
        cudaMemsetAsync(p_agg, 0, (size_t)NN*H*sizeof(float));
        k_msg<<<(NE+3)/4, 256>>>(edge_attr, edge_index,
                                 edge_w1 + (size_t)l*16*64, edge_b1 + (size_t)l*64);
        k_nodemm<<<(NN+63)/64, 256>>>(cur, nxt, root_w + (size_t)l*64*64, conv_b + (size_t)l*64, 1);
        float* tmp = cur; cur = nxt; nxt = tmp;
    }

    k_pool<<<(NN*H+255)/256, 256>>>(batch, cur);
    k_head<<<1, 256>>>(head_w1, head_b1, head_w2, head_b2, out);
}

// round 2
// speedup vs baseline: 1.0227x; 1.0227x over previous
#include <cuda_runtime.h>

#define NN 10000
#define NE 40000
#define NG 64
#define H  64
#define QC 4160   // 64*64 theta cols + 64 b2 cols

typedef unsigned long long ull;

// ---------------- scratch ----------------
__device__ float g_h0[NN*H];
__device__ float g_h1[NN*H];
__device__ float g_Q[(size_t)NN*QC];
__device__ float g_agg[NN*H];
__device__ float g_W2ext[H*QC];
__device__ float g_invdeg[NN];
__device__ float g_hg[NG*H];
__device__ float g_gcnt[NG];
// sorting scratch
__device__ int   g_cnt[NN];       // src histogram -> start offsets (cursor)
__device__ int   g_ideg[NN];      // dst histogram (degree)
__device__ int   g_perm[NE];
__device__ int   g_srcs[NE];
__device__ int   g_dsts[NE];
__device__ float g_eas[NE*16];

__device__ __forceinline__ float siluf(float x){
    return x * (1.0f/(1.0f+__expf(-x)));
}
__device__ __forceinline__ ull pack2(float x){
    ull r; asm("mov.b64 %0, {%1, %1};" : "=l"(r) : "f"(x)); return r;
}
__device__ __forceinline__ void ffma2(ull &d, ull a, ull b){
    asm("fma.rn.f32x2 %0, %1, %2, %0;" : "+l"(d) : "l"(a), "l"(b));
}
__device__ __forceinline__ float2 unpack2(ull v){
    float2 r; asm("mov.b64 {%0, %1}, %2;" : "=f"(r.x), "=f"(r.y) : "l"(v)); return r;
}

// ---------------- histograms ----------------
__global__ void k_hist(const int* __restrict__ ei){
    int e = blockIdx.x*256 + threadIdx.x;
    if(e < NE){
        atomicAdd(&g_cnt[ei[e]], 1);        // by src (for sort)
        atomicAdd(&g_ideg[ei[NE+e]], 1);    // by dst (for mean agg)
    }
}

__global__ void k_invdeg(){
    int v = blockIdx.x*256 + threadIdx.x;
    if(v < NN){ int d = g_ideg[v]; g_invdeg[v] = (d > 0) ? 1.0f/(float)d : 0.0f; }
}

// ---------------- exclusive scan of g_cnt -> g_cnt (start offsets) ----------------
__global__ void k_scan(){
    __shared__ int sp[1024];
    int t = threadIdx.x;           // 1024 threads
    const int CH = 10;             // 1024*10 >= NN
    int base = t*CH;
    int loc[CH];
    int sum = 0;
    #pragma unroll
    for(int i=0;i<CH;i++){
        int idx = base+i;
        int v = (idx < NN) ? g_cnt[idx] : 0;
        loc[i] = sum; sum += v;
    }
    sp[t] = sum;
    __syncthreads();
    for(int d=1; d<1024; d<<=1){
        int v = (t >= d) ? sp[t-d] : 0;
        __syncthreads();
        sp[t] += v;
        __syncthreads();
    }
    int off = (t > 0) ? sp[t-1] : 0;
    #pragma unroll
    for(int i=0;i<CH;i++){
        int idx = base+i;
        if(idx < NN) g_cnt[idx] = off + loc[i];
    }
}

// ---------------- scatter edges into src-sorted order ----------------
__global__ void k_scatter(const int* __restrict__ ei){
    int e = blockIdx.x*256 + threadIdx.x;
    if(e < NE){
        int s = ei[e];
        int pos = atomicAdd(&g_cnt[s], 1);
        g_srcs[pos] = s;
        g_dsts[pos] = ei[NE+e];
        g_perm[pos] = e;
    }
}

__global__ void k_gatherEA(const float* __restrict__ ea){
    int idx = blockIdx.x*256 + threadIdx.x;
    if(idx < NE*16){
        g_eas[idx] = ea[g_perm[idx>>4]*16 + (idx&15)];
    }
}

// ---------------- node-side [*,64]@[64,64] with fused epilogue ----------------
__global__ void k_nodemm(const float* __restrict__ A, float* __restrict__ out,
                         const float* __restrict__ W, const float* __restrict__ b,
                         int mode){
    __shared__ float Ws[H*H];
    __shared__ float As[64][H+1];
    int t = threadIdx.x;
    int base = blockIdx.x*64;
    for(int i=t;i<H*H;i+=256) Ws[i]=W[i];
    for(int i=t;i<64*H;i+=256){
        int r=i>>6, c=i&63; int v=base+r;
        As[r][c] = (v<NN) ? A[v*H+c] : 0.f;
    }
    __syncthreads();
    int vl=t>>2, ob=(t&3)*16;
    int v=base+vl;
    if(v>=NN) return;
    float acc[16];
    #pragma unroll
    for(int q=0;q<16;q++) acc[q]=b[ob+q];
    #pragma unroll 8
    for(int i=0;i<H;i++){
        float hv=As[vl][i];
        #pragma unroll
        for(int q=0;q<16;q++) acc[q] += hv*Ws[i*H+ob+q];
    }
    if(mode==0){
        #pragma unroll
        for(int q=0;q<16;q++) out[v*H+ob+q]=acc[q];
    } else {
        float inv = g_invdeg[v];
        #pragma unroll
        for(int q=0;q<16;q++){
            float val = g_agg[v*H+ob+q]*inv + acc[q];
            out[v*H+ob+q] = siluf(val);
        }
    }
}

// ---------------- permute edge_w2[l] -> W2ext ----------------
__global__ void k_transp(const float* __restrict__ w2, const float* __restrict__ b2){
    int idx = blockIdx.x*256 + threadIdx.x;
    if(idx < H*QC){
        int i = idx / QC;
        int c = idx % QC;
        float v;
        if(c < 4096){
            int j = c>>6, o = c&63;
            v = w2[j*4096 + i*64 + o];
        } else {
            v = b2[i*64 + (c-4096)];
        }
        g_W2ext[idx] = v;
    }
}

// ---------------- Q = h @ W2ext with packed fp32x2 FMA ----------------
__global__ void k_qgemm(const float* __restrict__ hin){
    __shared__ float As[64][64];    // [k][m]
    __shared__ float Bs[64][128];   // [k][n]
    int t = threadIdx.x;
    int bn = blockIdx.x*128;
    int bm = blockIdx.y*64;

    {
        int r = t>>2, c0 = (t&3)*16;
        int gr = bm + r;
        float4 v0,v1,v2,v3;
        if(gr < NN){
            const float4* p = (const float4*)(hin + gr*H + c0);
            v0=p[0]; v1=p[1]; v2=p[2]; v3=p[3];
        } else {
            v0=v1=v2=v3=make_float4(0.f,0.f,0.f,0.f);
        }
        As[c0+ 0][r]=v0.x; As[c0+ 1][r]=v0.y; As[c0+ 2][r]=v0.z; As[c0+ 3][r]=v0.w;
        As[c0+ 4][r]=v1.x; As[c0+ 5][r]=v1.y; As[c0+ 6][r]=v1.z; As[c0+ 7][r]=v1.w;
        As[c0+ 8][r]=v2.x; As[c0+ 9][r]=v2.y; As[c0+10][r]=v2.z; As[c0+11][r]=v2.w;
        As[c0+12][r]=v3.x; As[c0+13][r]=v3.y; As[c0+14][r]=v3.z; As[c0+15][r]=v3.w;
    }
    for(int i=t;i<64*32;i+=256){
        int r = i>>5, c = (i&31)*4;
        float4 val;
        if(bn + c < QC) val = *(const float4*)(g_W2ext + r*QC + bn + c);
        else            val = make_float4(0.f,0.f,0.f,0.f);
        *(float4*)&Bs[r][c] = val;
    }
    __syncthreads();

    int tx = t&15, ty = t>>4;
    ull acc[4][4];
    #pragma unroll
    for(int i=0;i<4;i++)
        #pragma unroll
        for(int j=0;j<4;j++) acc[i][j]=0ull;

    #pragma unroll 16
    for(int k=0;k<64;k++){
        float4 a = *(const float4*)&As[k][ty*4];
        ulonglong2 b01 = *(const ulonglong2*)&Bs[k][tx*8];
        ulonglong2 b23 = *(const ulonglong2*)&Bs[k][tx*8+4];
        ull ap0 = pack2(a.x), ap1 = pack2(a.y), ap2 = pack2(a.z), ap3 = pack2(a.w);
        ffma2(acc[0][0], ap0, b01.x); ffma2(acc[0][1], ap0, b01.y);
        ffma2(acc[0][2], ap0, b23.x); ffma2(acc[0][3], ap0, b23.y);
        ffma2(acc[1][0], ap1, b01.x); ffma2(acc[1][1], ap1, b01.y);
        ffma2(acc[1][2], ap1, b23.x); ffma2(acc[1][3], ap1, b23.y);
        ffma2(acc[2][0], ap2, b01.x); ffma2(acc[2][1], ap2, b01.y);
        ffma2(acc[2][2], ap2, b23.x); ffma2(acc[2][3], ap2, b23.y);
        ffma2(acc[3][0], ap3, b01.x); ffma2(acc[3][1], ap3, b01.y);
        ffma2(acc[3][2], ap3, b23.x); ffma2(acc[3][3], ap3, b23.y);
    }

    #pragma unroll
    for(int i=0;i<4;i++){
        int row = bm + ty*4 + i;
        if(row < NN){
            int col = bn + tx*8;
            if(col < QC){
                float2 p0 = unpack2(acc[i][0]);
                float2 p1 = unpack2(acc[i][1]);
                float2 p2 = unpack2(acc[i][2]);
                float2 p3 = unpack2(acc[i][3]);
                float4 o0 = make_float4(p0.x,p0.y,p1.x,p1.y);
                float4 o1 = make_float4(p2.x,p2.y,p3.x,p3.y);
                *(float4*)(g_Q + (size_t)row*QC + col)     = o0;
                *(float4*)(g_Q + (size_t)row*QC + col + 4) = o1;
            }
        }
    }
}

// ---------------- per-edge message over src-sorted edges ----------------
__global__ void k_msg(const float* __restrict__ w1, const float* __restrict__ b1){
    __shared__ float W1s[16*64];
    __shared__ float b1s[64];
    __shared__ float sf[4][64];
    int t = threadIdx.x;
    for(int i=t;i<16*64;i+=256) W1s[i]=w1[i];
    if(t<64) b1s[t]=b1[t];
    __syncthreads();

    int el = t>>6;
    int o  = t&63;
    int e  = blockIdx.x*4 + el;
    int src=0, dst=0;
    if(e < NE){
        src = g_srcs[e];
        dst = g_dsts[e];
        const float* eap = g_eas + e*16;
        float s = b1s[o];
        #pragma unroll
        for(int j=0;j<16;j++) s += eap[j]*W1s[j*64+o];
        sf[el][o] = siluf(s);
    }
    __syncthreads();
    if(e < NE){
        const float* q = g_Q + (size_t)src*QC;
        float msg = __ldg(q + 4096 + o);
        #pragma unroll 8
        for(int j=0;j<64;j++) msg += sf[el][j]*__ldg(q + j*64 + o);
        atomicAdd(&g_agg[dst*H + o], msg);
    }
}

// ---------------- global mean pool ----------------
__global__ void k_pool(const int* __restrict__ batch, const float* __restrict__ hfin){
    int idx = blockIdx.x*256 + threadIdx.x;
    if(idx < NN*H){
        int v = idx>>6, o = idx&63;
        int g = batch[v];
        atomicAdd(&g_hg[g*H + o], hfin[idx]);
        if(o == 0) atomicAdd(&g_gcnt[g], 1.0f);
    }
}

// ---------------- head MLP ----------------
__global__ void k_head(const float* __restrict__ w1, const float* __restrict__ b1,
                       const float* __restrict__ w2, const float* __restrict__ b2,
                       float* __restrict__ out){
    __shared__ float W1s[64*64];
    __shared__ float hgn[64*64];
    __shared__ float t1[64*64];
    int t = threadIdx.x;
    for(int i=t;i<4096;i+=256) W1s[i]=w1[i];
    for(int i=t;i<4096;i+=256){
        int g = i>>6;
        float c = g_gcnt[g];
        hgn[i] = g_hg[i] / fmaxf(c, 1.0f);
    }
    __syncthreads();
    int g = t>>2, ob = (t&3)*16;
    float acc[16];
    #pragma unroll
    for(int q=0;q<16;q++) acc[q]=b1[ob+q];
    for(int i=0;i<64;i++){
        float hv = hgn[g*64+i];
        #pragma unroll
        for(int q=0;q<16;q++) acc[q] += hv*W1s[i*64+ob+q];
    }
    #pragma unroll
    for(int q=0;q<16;q++) t1[g*64+ob+q] = siluf(acc[q]);
    __syncthreads();
    if(t < 64){
        float s = b2[0];
        for(int o=0;o<64;o++) s += t1[t*64+o]*w2[o];
        out[t] = s;
    }
}

// ---------------- launch ----------------
extern "C" void kernel_launch(void* const* d_in, const int* in_sizes, int n_in,
                              void* d_out, int out_size){
    const float* x         = (const float*)d_in[0];
    const float* edge_attr = (const float*)d_in[1];
    const int*   edge_index= (const int*)  d_in[2];
    const int*   batch     = (const int*)  d_in[3];
    const float* proj_w    = (const float*)d_in[4];
    const float* proj_b    = (const float*)d_in[5];
    const float* edge_w1   = (const float*)d_in[6];
    const float* edge_b1   = (const float*)d_in[7];
    const float* edge_w2   = (const float*)d_in[8];
    const float* edge_b2   = (const float*)d_in[9];
    const float* root_w    = (const float*)d_in[10];
    const float* conv_b    = (const float*)d_in[11];
    const float* head_w1   = (const float*)d_in[12];
    const float* head_b1   = (const float*)d_in[13];
    const float* head_w2   = (const float*)d_in[14];
    const float* head_b2   = (const float*)d_in[15];
    float* out = (float*)d_out;

    void *p_agg, *p_hg, *p_gcnt, *p_h0, *p_h1, *p_cnt, *p_ideg;
    cudaGetSymbolAddress(&p_agg,  g_agg);
    cudaGetSymbolAddress(&p_hg,   g_hg);
    cudaGetSymbolAddress(&p_gcnt, g_gcnt);
    cudaGetSymbolAddress(&p_h0,   g_h0);
    cudaGetSymbolAddress(&p_h1,   g_h1);
    cudaGetSymbolAddress(&p_cnt,  g_cnt);
    cudaGetSymbolAddress(&p_ideg, g_ideg);
    float* h0 = (float*)p_h0;
    float* h1 = (float*)p_h1;

    cudaMemsetAsync(p_cnt,  0, NN*sizeof(int));
    cudaMemsetAsync(p_ideg, 0, NN*sizeof(int));
    cudaMemsetAsync(p_hg,   0, NG*H*sizeof(float));
    cudaMemsetAsync(p_gcnt, 0, NG*sizeof(float));

    // sort edges by src (counting sort), once per launch
    k_hist<<<(NE+255)/256, 256>>>(edge_index);
    k_invdeg<<<(NN+255)/256, 256>>>();
    k_scan<<<1, 1024>>>();
    k_scatter<<<(NE+255)/256, 256>>>(edge_index);
    k_gatherEA<<<(NE*16+255)/256, 256>>>(edge_attr);

    float* cur = h0;
    float* nxt = h1;
    k_nodemm<<<(NN+63)/64, 256>>>(x, cur, proj_w, proj_b, 0);

    for(int l=0;l<3;l++){
        k_transp<<<(H*QC+255)/256, 256>>>(edge_w2 + (size_t)l*64*4096, edge_b2 + (size_t)l*4096);
        k_qgemm<<<dim3((QC+127)/128, (NN+63)/64), 256>>>(cur);
        cudaMemsetAsync(p_agg, 0, (size_t)NN*H*sizeof(float));
        k_msg<<<(NE+3)/4, 256>>>(edge_w1 + (size_t)l*16*64, edge_b1 + (size_t)l*64);
        k_nodemm<<<(NN+63)/64, 256>>>(cur, nxt, root_w + (size_t)l*64*64, conv_b + (size_t)l*64, 1);
        float* tmp = cur; cur = nxt; nxt = tmp;
    }

    k_pool<<<(NN*H+255)/256, 256>>>(batch, cur);
    k_head<<<1, 256>>>(head_w1, head_b1, head_w2, head_b2, out);
}

// round 3
// speedup vs baseline: 1.2402x; 1.2127x over previous
#include <cuda_runtime.h>

#define NN 10000
#define NE 40000
#define NG 64
#define H  64
#define QC 4160   // 64*64 theta cols + 64 b2 cols

typedef unsigned long long ull;

// ---------------- scratch ----------------
__device__ float g_h0[NN*H];
__device__ float g_h1[NN*H];
__device__ float g_Q[(size_t)NN*QC];
__device__ float g_agg[NN*H];
__device__ float g_W2ext[H*QC];
__device__ float g_invdeg[NN];
__device__ float g_hg[NG*H];
__device__ float g_gcnt[NG];
__device__ int   g_cnt[NN];
__device__ int   g_ideg[NN];
__device__ int   g_perm[NE];
__device__ int   g_srcs[NE];
__device__ int   g_dsts[NE];
__device__ float g_eas[NE*16];

__device__ __forceinline__ float siluf(float x){
    return x * (1.0f/(1.0f+__expf(-x)));
}
__device__ __forceinline__ ull pack2(float x){
    ull r; asm("mov.b64 %0, {%1, %1};" : "=l"(r) : "f"(x)); return r;
}
__device__ __forceinline__ void ffma2(ull &d, ull a, ull b){
    asm("fma.rn.f32x2 %0, %1, %2, %0;" : "+l"(d) : "l"(a), "l"(b));
}
__device__ __forceinline__ float2 unpack2(ull v){
    float2 r; asm("mov.b64 {%0, %1}, %2;" : "=f"(r.x), "=f"(r.y) : "l"(v)); return r;
}

// ---------------- node-side [*,64]@[64,64] with fused epilogue ----------------
__global__ void k_nodemm(const float* __restrict__ A, float* __restrict__ out,
                         const float* __restrict__ W, const float* __restrict__ b,
                         int mode){
    __shared__ float Ws[H*H];
    __shared__ float As[64][H+1];
    int t = threadIdx.x;
    int base = blockIdx.x*64;
    for(int i=t;i<H*H;i+=256) Ws[i]=W[i];
    for(int i=t;i<64*H;i+=256){
        int r=i>>6, c=i&63; int v=base+r;
        As[r][c] = (v<NN) ? A[v*H+c] : 0.f;
    }
    __syncthreads();
    int vl=t>>2, ob=(t&3)*16;
    int v=base+vl;
    if(v>=NN) return;
    float acc[16];
    #pragma unroll
    for(int q=0;q<16;q++) acc[q]=b[ob+q];
    #pragma unroll 8
    for(int i=0;i<H;i++){
        float hv=As[vl][i];
        #pragma unroll
        for(int q=0;q<16;q++) acc[q] += hv*Ws[i*H+ob+q];
    }
    if(mode==0){
        #pragma unroll
        for(int q=0;q<16;q++) out[v*H+ob+q]=acc[q];
    } else {
        float inv = g_invdeg[v];
        #pragma unroll
        for(int q=0;q<16;q++){
            float val = g_agg[v*H+ob+q]*inv + acc[q];
            out[v*H+ob+q] = siluf(val);
        }
    }
}

// ---------------- permute edge_w2[l] -> W2ext ----------------
__global__ void k_transp(const float* __restrict__ w2, const float* __restrict__ b2){
    int idx = blockIdx.x*256 + threadIdx.x;
    if(idx < H*QC){
        int i = idx / QC;
        int c = idx % QC;
        float v;
        if(c < 4096){
            int j = c>>6, o = c&63;
            v = w2[j*4096 + i*64 + o];
        } else {
            v = b2[i*64 + (c-4096)];
        }
        g_W2ext[idx] = v;
    }
}

// ---------------- histograms ----------------
__global__ void k_hist(const int* __restrict__ ei){
    int e = blockIdx.x*256 + threadIdx.x;
    if(e < NE){
        atomicAdd(&g_cnt[ei[e]], 1);
        atomicAdd(&g_ideg[ei[NE+e]], 1);
    }
}

// ---------------- Q = h @ W2ext : 128x128 tile, FFMA2, A pre-duplicated ----------------
__global__ void __launch_bounds__(256,2) k_qgemm(const float* __restrict__ hin){
    extern __shared__ float smem[];
    float* As2 = smem;            // [64][256]: k*256 + m*2 (+0/1 duplicated) = 64KB
    float* Bs  = smem + 64*256;   // [64][128] = 32KB
    int t = threadIdx.x;
    int bn = blockIdx.x*128;
    int bm = blockIdx.y*128;

    // A tile: rows bm..bm+127, 64 cols, stored transposed with duplicated pairs
    {
        int r  = t>>1;
        int c0 = (t&1)*32;
        int gr = bm + r;
        #pragma unroll
        for(int i=0;i<8;i++){
            float4 v = (gr<NN) ? *(const float4*)(hin + gr*H + c0 + i*4)
                               : make_float4(0.f,0.f,0.f,0.f);
            *(float2*)&As2[(c0+i*4+0)*256 + r*2] = make_float2(v.x,v.x);
            *(float2*)&As2[(c0+i*4+1)*256 + r*2] = make_float2(v.y,v.y);
            *(float2*)&As2[(c0+i*4+2)*256 + r*2] = make_float2(v.z,v.z);
            *(float2*)&As2[(c0+i*4+3)*256 + r*2] = make_float2(v.w,v.w);
        }
    }
    // B tile
    for(int i=t;i<64*32;i+=256){
        int r = i>>5, c = (i&31)*4;
        float4 v = (bn + c < QC) ? *(const float4*)(g_W2ext + r*QC + bn + c)
                                 : make_float4(0.f,0.f,0.f,0.f);
        *(float4*)&Bs[r*128 + c] = v;
    }
    __syncthreads();

    int tx = t&15, ty = t>>4;
    ull acc[8][4];
    #pragma unroll
    for(int i=0;i<8;i++)
        #pragma unroll
        for(int j=0;j<4;j++) acc[i][j]=0ull;

    const float* aBase = As2 + ty*16;
    const float* bBase = Bs  + tx*8;

    #pragma unroll 8
    for(int k=0;k<64;k++){
        ulonglong2 a0 = *(const ulonglong2*)(aBase + k*256);
        ulonglong2 a1 = *(const ulonglong2*)(aBase + k*256 + 4);
        ulonglong2 a2 = *(const ulonglong2*)(aBase + k*256 + 8);
        ulonglong2 a3 = *(const ulonglong2*)(aBase + k*256 + 12);
        ulonglong2 b0 = *(const ulonglong2*)(bBase + k*128);
        ulonglong2 b1 = *(const ulonglong2*)(bBase + k*128 + 4);
        ull av[8] = {a0.x,a0.y,a1.x,a1.y,a2.x,a2.y,a3.x,a3.y};
        ull bv[4] = {b0.x,b0.y,b1.x,b1.y};
        #pragma unroll
        for(int i=0;i<8;i++){
            ffma2(acc[i][0], av[i], bv[0]);
            ffma2(acc[i][1], av[i], bv[1]);
            ffma2(acc[i][2], av[i], bv[2]);
            ffma2(acc[i][3], av[i], bv[3]);
        }
    }

    int col = bn + tx*8;
    if(col < QC){
        #pragma unroll
        for(int i=0;i<8;i++){
            int row = bm + ty*8 + i;
            if(row < NN){
                float2 p0 = unpack2(acc[i][0]);
                float2 p1 = unpack2(acc[i][1]);
                float2 p2 = unpack2(acc[i][2]);
                float2 p3 = unpack2(acc[i][3]);
                *(float4*)(g_Q + (size_t)row*QC + col)     = make_float4(p0.x,p0.y,p1.x,p1.y);
                *(float4*)(g_Q + (size_t)row*QC + col + 4) = make_float4(p2.x,p2.y,p3.x,p3.y);
            }
        }
    }
}

// ---------------- scan (+ fused invdeg) ----------------
__global__ void k_scan(){
    __shared__ int sp[1024];
    int t = threadIdx.x;
    const int CH = 10;
    int base = t*CH;
    int loc[CH];
    int sum = 0;
    #pragma unroll
    for(int i=0;i<CH;i++){
        int idx = base+i;
        int v = (idx < NN) ? g_cnt[idx] : 0;
        loc[i] = sum; sum += v;
    }
    sp[t] = sum;
    __syncthreads();
    for(int d=1; d<1024; d<<=1){
        int v = (t >= d) ? sp[t-d] : 0;
        __syncthreads();
        sp[t] += v;
        __syncthreads();
    }
    int off = (t > 0) ? sp[t-1] : 0;
    #pragma unroll
    for(int i=0;i<CH;i++){
        int idx = base+i;
        if(idx < NN){
            g_cnt[idx] = off + loc[i];
            int d = g_ideg[idx];
            g_invdeg[idx] = (d > 0) ? 1.0f/(float)d : 0.0f;
        }
    }
}

__global__ void k_scatter(const int* __restrict__ ei){
    int e = blockIdx.x*256 + threadIdx.x;
    if(e < NE){
        int s = ei[e];
        int pos = atomicAdd(&g_cnt[s], 1);
        g_srcs[pos] = s;
        g_dsts[pos] = ei[NE+e];
        g_perm[pos] = e;
    }
}

__global__ void k_gatherEA(const float* __restrict__ ea){
    int idx = blockIdx.x*256 + threadIdx.x;
    if(idx < NE*16){
        g_eas[idx] = ea[g_perm[idx>>4]*16 + (idx&15)];
    }
}

// ---------------- per-edge message: 16 edges/block, float4 gathers, FFMA2 ----------------
__global__ void k_msg(const float* __restrict__ w1, const float* __restrict__ b1){
    __shared__ float W1s[16*64];
    __shared__ float b1s[64];
    __shared__ float eas[16][16];
    __shared__ float sf[16][64];
    __shared__ int   ss[16], ds[16];
    int t = threadIdx.x;
    int e0 = blockIdx.x*16;

    for(int i=t;i<16*64;i+=256) W1s[i]=w1[i];
    if(t<64) b1s[t]=b1[t];
    {
        int e = e0 + (t>>4);
        eas[t>>4][t&15] = (e<NE) ? g_eas[e*16 + (t&15)] : 0.f;
    }
    if(t<16){
        int e = e0 + t;
        ss[t] = (e<NE) ? g_srcs[e] : 0;
        ds[t] = (e<NE) ? g_dsts[e] : 0;
    }
    __syncthreads();

    int s = t>>4, l = t&15, o0 = l*4;
    // sfeat: 4 outputs per thread
    {
        float v0=b1s[o0], v1=b1s[o0+1], v2=b1s[o0+2], v3=b1s[o0+3];
        #pragma unroll
        for(int j=0;j<16;j++){
            float ej = eas[s][j];
            v0 += ej*W1s[j*64+o0];
            v1 += ej*W1s[j*64+o0+1];
            v2 += ej*W1s[j*64+o0+2];
            v3 += ej*W1s[j*64+o0+3];
        }
        sf[s][o0]   = siluf(v0);
        sf[s][o0+1] = siluf(v1);
        sf[s][o0+2] = siluf(v2);
        sf[s][o0+3] = siluf(v3);
    }
    __syncthreads();

    int e = e0 + s;
    if(e < NE){
        const float* q = g_Q + (size_t)ss[s]*QC;
        ulonglong2 acc = *(const ulonglong2*)(q + 4096 + o0);   // b2 part
        #pragma unroll 16
        for(int j=0;j<64;j++){
            ulonglong2 qv = *(const ulonglong2*)(q + j*64 + o0);
            ull sp = pack2(sf[s][j]);
            ffma2(acc.x, sp, qv.x);
            ffma2(acc.y, sp, qv.y);
        }
        float2 r0 = unpack2(acc.x);
        float2 r1 = unpack2(acc.y);
        float* ap = g_agg + ds[s]*H + o0;
        atomicAdd(ap,   r0.x);
        atomicAdd(ap+1, r0.y);
        atomicAdd(ap+2, r1.x);
        atomicAdd(ap+3, r1.y);
    }
}

// ---------------- global mean pool ----------------
__global__ void k_pool(const int* __restrict__ batch, const float* __restrict__ hfin){
    int idx = blockIdx.x*256 + threadIdx.x;
    if(idx < NN*H){
        int v = idx>>6, o = idx&63;
        int g = batch[v];
        atomicAdd(&g_hg[g*H + o], hfin[idx]);
        if(o == 0) atomicAdd(&g_gcnt[g], 1.0f);
    }
}

// ---------------- head MLP ----------------
__global__ void k_head(const float* __restrict__ w1, const float* __restrict__ b1,
                       const float* __restrict__ w2, const float* __restrict__ b2,
                       float* __restrict__ out){
    __shared__ float W1s[64*64];
    __shared__ float hgn[64*64];
    __shared__ float t1[64*64];
    int t = threadIdx.x;
    for(int i=t;i<4096;i+=256) W1s[i]=w1[i];
    for(int i=t;i<4096;i+=256){
        int g = i>>6;
        float c = g_gcnt[g];
        hgn[i] = g_hg[i] / fmaxf(c, 1.0f);
    }
    __syncthreads();
    int g = t>>2, ob = (t&3)*16;
    float acc[16];
    #pragma unroll
    for(int q=0;q<16;q++) acc[q]=b1[ob+q];
    for(int i=0;i<64;i++){
        float hv = hgn[g*64+i];
        #pragma unroll
        for(int q=0;q<16;q++) acc[q] += hv*W1s[i*64+ob+q];
    }
    #pragma unroll
    for(int q=0;q<16;q++) t1[g*64+ob+q] = siluf(acc[q]);
    __syncthreads();
    if(t < 64){
        float s = b2[0];
        for(int o=0;o<64;o++) s += t1[t*64+o]*w2[o];
        out[t] = s;
    }
}

// ---------------- launch ----------------
extern "C" void kernel_launch(void* const* d_in, const int* in_sizes, int n_in,
                              void* d_out, int out_size){
    const float* x         = (const float*)d_in[0];
    const float* edge_attr = (const float*)d_in[1];
    const int*   edge_index= (const int*)  d_in[2];
    const int*   batch     = (const int*)  d_in[3];
    const float* proj_w    = (const float*)d_in[4];
    const float* proj_b    = (const float*)d_in[5];
    const float* edge_w1   = (const float*)d_in[6];
    const float* edge_b1   = (const float*)d_in[7];
    const float* edge_w2   = (const float*)d_in[8];
    const float* edge_b2   = (const float*)d_in[9];
    const float* root_w    = (const float*)d_in[10];
    const float* conv_b    = (const float*)d_in[11];
    const float* head_w1   = (const float*)d_in[12];
    const float* head_b1   = (const float*)d_in[13];
    const float* head_w2   = (const float*)d_in[14];
    const float* head_b2   = (const float*)d_in[15];
    float* out = (float*)d_out;

    void *p_agg, *p_hg, *p_gcnt, *p_h0, *p_h1, *p_cnt, *p_ideg;
    cudaGetSymbolAddress(&p_agg,  g_agg);
    cudaGetSymbolAddress(&p_hg,   g_hg);
    cudaGetSymbolAddress(&p_gcnt, g_gcnt);
    cudaGetSymbolAddress(&p_h0,   g_h0);
    cudaGetSymbolAddress(&p_h1,   g_h1);
    cudaGetSymbolAddress(&p_cnt,  g_cnt);
    cudaGetSymbolAddress(&p_ideg, g_ideg);
    float* h0 = (float*)p_h0;
    float* h1 = (float*)p_h1;

    cudaFuncSetAttribute(k_qgemm, cudaFuncAttributeMaxDynamicSharedMemorySize, 96*1024);

    cudaMemsetAsync(p_cnt,  0, NN*sizeof(int));
    cudaMemsetAsync(p_ideg, 0, NN*sizeof(int));
    cudaMemsetAsync(p_hg,   0, NG*H*sizeof(float));
    cudaMemsetAsync(p_gcnt, 0, NG*sizeof(float));

    float* cur = h0;
    float* nxt = h1;

    // launch order chosen so the profiler's fixed 4th-kernel capture lands on k_qgemm
    k_nodemm<<<(NN+63)/64, 256>>>(x, cur, proj_w, proj_b, 0);                    // 1
    k_transp<<<(H*QC+255)/256, 256>>>(edge_w2, edge_b2);                          // 2
    k_hist<<<(NE+255)/256, 256>>>(edge_index);                                    // 3
    k_qgemm<<<dim3((QC+127)/128, (NN+127)/128), 256, 96*1024>>>(cur);             // 4 (profiled)
    k_scan<<<1, 1024>>>();                                                        // 5
    k_scatter<<<(NE+255)/256, 256>>>(edge_index);                                 // 6
    k_gatherEA<<<(NE*16+255)/256, 256>>>(edge_attr);                              // 7

    for(int l=0;l<3;l++){
        if(l > 0){
            k_transp<<<(H*QC+255)/256, 256>>>(edge_w2 + (size_t)l*64*4096, edge_b2 + (size_t)l*4096);
            k_qgemm<<<dim3((QC+127)/128, (NN+127)/128), 256, 96*1024>>>(cur);
        }
        cudaMemsetAsync(p_agg, 0, (size_t)NN*H*sizeof(float));
        k_msg<<<(NE+15)/16, 256>>>(edge_w1 + (size_t)l*16*64, edge_b1 + (size_t)l*64);
        k_nodemm<<<(NN+63)/64, 256>>>(cur, nxt, root_w + (size_t)l*64*64, conv_b + (size_t)l*64, 1);
        float* tmp = cur; cur = nxt; nxt = tmp;
    }

    k_pool<<<(NN*H+255)/256, 256>>>(batch, cur);
    k_head<<<1, 256>>>(head_w1, head_b1, head_w2, head_b2, out);
}